// round 1
// baseline (speedup 1.0000x reference)
#include <cuda_runtime.h>
#include <math.h>

// Problem constants (fixed by the dataset)
#define BB 8
#define FF 16
#define NN 2048
#define JS 4
#define NCOLS 21          // 1 + 4 + 16
#define OUT_ELEMS (BB*FF*NCOLS)

// Scratch: S1[b][j][f][m] as a 512 x 2048 row-major matrix, row = (b*4+j)*16+f
__device__ float g_S1[BB * JS * FF * NN];

// ---------------------------------------------------------------------------
// Zero-init phi (d_out is poisoned to 0xAA by the harness)
// ---------------------------------------------------------------------------
__global__ void zero_phi_kernel(float* __restrict__ out) {
    int i = blockIdx.x * blockDim.x + threadIdx.x;
    if (i < OUT_ELEMS) out[i] = 0.0f;
}

// ---------------------------------------------------------------------------
// phi0[b,f] = sum_n x[b,f,n] * lowpass[n]   (exact fp32 — signed sum, can be ~0)
// one block per (b,f): 128 blocks x 256 threads
// ---------------------------------------------------------------------------
__global__ void phi0_kernel(const float* __restrict__ x,
                            const float* __restrict__ lp,
                            float* __restrict__ out) {
    int r = blockIdx.x;                     // r = b*16 + f
    const float* xr = x + (size_t)r * NN;
    float s = 0.0f;
    for (int n = threadIdx.x; n < NN; n += 256) s += xr[n] * lp[n];
    // block reduce
    __shared__ float red[8];
    #pragma unroll
    for (int o = 16; o; o >>= 1) s += __shfl_xor_sync(0xffffffffu, s, o);
    if ((threadIdx.x & 31) == 0) red[threadIdx.x >> 5] = s;
    __syncthreads();
    if (threadIdx.x < 8) {
        s = red[threadIdx.x];
        #pragma unroll
        for (int o = 4; o; o >>= 1) s += __shfl_xor_sync(0xffu, s, o);
        if (threadIdx.x == 0) out[r * NCOLS + 0] = s;
    }
}

// ---------------------------------------------------------------------------
// Fused GEMM + |.| + lowpass-reduction epilogue.
//   C[r, m] = sum_n A[r, n] * psi[j][n][m]
//   LAYER==1: A = x (M=128 rows, row=b*16+f). Writes S1[(b*4+j)*16+f][m]=|C|,
//             and atomically accumulates phi[b,f,1+j] += sum_m |C| * lp[m].
//   LAYER==2: A = g_S1 (M=512 rows, row=(b*4+j1)*16+f). Accumulates
//             phi[b,f,5+j1*4+j2] += sum_m |C| * lp[m].   (S2 never stored)
// Tiles: BM=64, BN=64, BK=16; 256 threads; 4x4 register micro-tile.
// Grid: x = N-tiles (32), y = M-tiles, z = j (4).
// ---------------------------------------------------------------------------
template <int LAYER>
__global__ __launch_bounds__(256)
void gemm_layer_kernel(const float* __restrict__ Ain,
                       const float* __restrict__ psi,
                       const float* __restrict__ lp,
                       float* __restrict__ phi) {
    constexpr int BM = 64, BN = 64, BK = 16;
    __shared__ __align__(16) float As[BK][BM + 4];  // +4 pad, row stride 68 (16B-aligned)
    __shared__ __align__(16) float Bs[BK][BN];
    __shared__ float sred[BM];

    const float* A = (LAYER == 1) ? Ain : g_S1;

    const int j  = blockIdx.z;
    const int m0 = blockIdx.y * BM;     // A-row tile base
    const int n0 = blockIdx.x * BN;     // psi-column tile base
    const int tid = threadIdx.x;
    const int tx = tid & 15;            // 16 x 16 thread grid
    const int ty = tid >> 4;

    const float* Bmat = psi + (size_t)j * NN * NN;

    if (tid < BM) sred[tid] = 0.0f;

    float acc[4][4] = {};

    // global-load assignments
    const int arow = tid >> 2, ac4 = tid & 3;    // A tile: 64 rows x 16 cols (float4)
    const int brow = tid >> 4, bc4 = tid & 15;   // B tile: 16 rows x 64 cols (float4)

    const float* aptr = A + (size_t)(m0 + arow) * NN + ac4 * 4;
    const float* bptr = Bmat + (size_t)brow * NN + n0 + bc4 * 4;

    for (int k0 = 0; k0 < NN; k0 += BK) {
        float4 av = *(const float4*)(aptr + k0);
        float4 bv = *(const float4*)(bptr + (size_t)k0 * NN);
        __syncthreads();  // covers sred init on iter 0, and prior-iter reads
        As[ac4 * 4 + 0][arow] = av.x;
        As[ac4 * 4 + 1][arow] = av.y;
        As[ac4 * 4 + 2][arow] = av.z;
        As[ac4 * 4 + 3][arow] = av.w;
        *(float4*)&Bs[brow][bc4 * 4] = bv;
        __syncthreads();

        #pragma unroll
        for (int kk = 0; kk < BK; kk++) {
            float4 a = *(const float4*)&As[kk][ty * 4];
            float4 b = *(const float4*)&Bs[kk][tx * 4];
            acc[0][0] += a.x * b.x; acc[0][1] += a.x * b.y;
            acc[0][2] += a.x * b.z; acc[0][3] += a.x * b.w;
            acc[1][0] += a.y * b.x; acc[1][1] += a.y * b.y;
            acc[1][2] += a.y * b.z; acc[1][3] += a.y * b.w;
            acc[2][0] += a.z * b.x; acc[2][1] += a.z * b.y;
            acc[2][2] += a.z * b.z; acc[2][3] += a.z * b.w;
            acc[3][0] += a.w * b.x; acc[3][1] += a.w * b.y;
            acc[3][2] += a.w * b.z; acc[3][3] += a.w * b.w;
        }
    }

    // Epilogue: abs, optional S1 store, lowpass partial reduction
    #pragma unroll
    for (int i = 0; i < 4; i++) {
        const int ar = m0 + ty * 4 + i;          // A-row (global)
        float p = 0.0f;
        #pragma unroll
        for (int jj = 0; jj < 4; jj++) {
            const int m = n0 + tx * 4 + jj;
            float v = fabsf(acc[i][jj]);
            if (LAYER == 1) {
                const int b = ar >> 4, f = ar & 15;
                g_S1[(size_t)(((b * JS + j) << 4) + f) * NN + m] = v;
            }
            p += v * __ldg(&lp[m]);
        }
        atomicAdd(&sred[ty * 4 + i], p);
    }
    __syncthreads();

    if (tid < BM) {
        const int ar = m0 + tid;
        int b, f, col;
        if (LAYER == 1) { b = ar >> 4; f = ar & 15; col = 1 + j; }
        else { b = ar >> 6; int j1 = (ar >> 4) & 3; f = ar & 15; col = 5 + j1 * 4 + j; }
        atomicAdd(&phi[(size_t)(b * FF + f) * NCOLS + col], sred[tid]);
    }
}

// ---------------------------------------------------------------------------
// Launch: zero -> phi0 -> layer1 (writes S1 + phi[:,1:5]) -> layer2 (phi[:,5:21])
// ---------------------------------------------------------------------------
extern "C" void kernel_launch(void* const* d_in, const int* in_sizes, int n_in,
                              void* d_out, int out_size) {
    const float* x   = (const float*)d_in[0];   // (8,16,2048)
    const float* psi = (const float*)d_in[1];   // (4,2048,2048)
    const float* lp  = (const float*)d_in[2];   // (2048,)
    float* out = (float*)d_out;                 // (8,16,21)
    (void)in_sizes; (void)n_in; (void)out_size;

    zero_phi_kernel<<<(OUT_ELEMS + 255) / 256, 256>>>(out);
    phi0_kernel<<<BB * FF, 256>>>(x, lp, out);
    // layer 1: M = 128 rows -> 2 M-tiles, 32 N-tiles, 4 j
    gemm_layer_kernel<1><<<dim3(32, 2, 4), 256>>>(x, psi, lp, out);
    // layer 2: M = 512 rows -> 8 M-tiles, 32 N-tiles, 4 j
    gemm_layer_kernel<2><<<dim3(32, 8, 4), 256>>>(nullptr, psi, lp, out);
}